// round 2
// baseline (speedup 1.0000x reference)
#include <cuda_runtime.h>

#define NN 20000
#define EE 320000
#define DD 1280
#define GG 64
#define FPD 65

// ---------------- scratch (static __device__ allocations only) ----------------
__device__ float g_h[(size_t)NN * DD];    // GEMM output (pre-aggregation)
__device__ float g_act[(size_t)NN * DD];  // aggregated + activated features
__device__ float g_deg[NN];
__device__ float g_dis[NN];
__device__ float g_norm[EE];
__device__ float g_pool[GG * 320];
__device__ float g_cnt[GG];
__device__ float g_t1[GG * 1024];
__device__ float g_t2[GG * 128];
__device__ float g_cat[GG * 193];
__device__ float g_t3[GG * 512];

// ---------------- degree / norm ----------------
__global__ void k_deg(const int* __restrict__ dst) {
    int i = blockIdx.x * blockDim.x + threadIdx.x;
    if (i < EE) {
        atomicAdd(&g_deg[dst[i]], 1.0f);
    } else if (i < EE + NN) {
        atomicAdd(&g_deg[i - EE], 1.0f);  // self-loop
    }
}

__global__ void k_dis() {
    int i = blockIdx.x * blockDim.x + threadIdx.x;
    if (i < NN) {
        float d = g_deg[i];
        g_dis[i] = (d > 0.0f) ? rsqrtf(d) : 0.0f;
    }
}

__global__ void k_norm(const int* __restrict__ src, const int* __restrict__ dst) {
    int i = blockIdx.x * blockDim.x + threadIdx.x;
    if (i < EE) g_norm[i] = g_dis[src[i]] * g_dis[dst[i]];
}

// ---------------- fp32 tiled GEMM: C[M,Nout] = A[M,K] @ B[K,Nout] ----------------
// BM=128, BN=64, BK=16, 256 threads, 8x4 per-thread tile.
// Requires: K % 16 == 0, Nout % 64 == 0, row-major everything.
__global__ __launch_bounds__(256) void k_gemm(
    const float* __restrict__ A, const float* __restrict__ B,
    float* __restrict__ C, int M, int K, int Nout) {
    __shared__ float As[16][132];
    __shared__ float Bs[16][64];

    int t = threadIdx.x;
    int m0 = blockIdx.y * 128;
    int n0 = blockIdx.x * 64;
    int tx = t & 15;   // 16 cols of threads -> 64 N
    int ty = t >> 4;   // 16 rows of threads -> 128 M

    float acc[8][4];
#pragma unroll
    for (int i = 0; i < 8; i++)
#pragma unroll
        for (int j = 0; j < 4; j++) acc[i][j] = 0.0f;

    for (int k0 = 0; k0 < K; k0 += 16) {
        // load A tile (128x16) transposed into As: 512 float4, 2 per thread
#pragma unroll
        for (int i = 0; i < 2; i++) {
            int v = t * 2 + i;       // 0..511
            int row = v >> 2;        // 0..127
            int kk = (v & 3) * 4;
            float4 a4;
            if (m0 + row < M) {
                a4 = *(const float4*)&A[(size_t)(m0 + row) * K + k0 + kk];
            } else {
                a4 = make_float4(0.f, 0.f, 0.f, 0.f);
            }
            As[kk + 0][row] = a4.x;
            As[kk + 1][row] = a4.y;
            As[kk + 2][row] = a4.z;
            As[kk + 3][row] = a4.w;
        }
        // load B tile (16x64): 256 float4, 1 per thread
        {
            int kk = t >> 4;         // 0..15
            int n = (t & 15) * 4;
            float4 b4 = *(const float4*)&B[(size_t)(k0 + kk) * Nout + n0 + n];
            *(float4*)&Bs[kk][n] = b4;
        }
        __syncthreads();

#pragma unroll
        for (int kk = 0; kk < 16; kk++) {
            float ar[8], br[4];
#pragma unroll
            for (int i = 0; i < 8; i++) ar[i] = As[kk][ty * 8 + i];
#pragma unroll
            for (int j = 0; j < 4; j++) br[j] = Bs[kk][tx * 4 + j];
#pragma unroll
            for (int i = 0; i < 8; i++)
#pragma unroll
                for (int j = 0; j < 4; j++) acc[i][j] += ar[i] * br[j];
        }
        __syncthreads();
    }

#pragma unroll
    for (int i = 0; i < 8; i++) {
        int row = m0 + ty * 8 + i;
        if (row < M) {
            float4 c4 = make_float4(acc[i][0], acc[i][1], acc[i][2], acc[i][3]);
            *(float4*)&C[(size_t)row * Nout + n0 + tx * 4] = c4;
        }
    }
}

// ---------------- edge scatter: out[dst] += h[src] * norm ----------------
// one block per (edge or self-loop), threads stride over feature float4s
__global__ __launch_bounds__(128) void k_scatter(
    const int* __restrict__ src, const int* __restrict__ dst,
    const float* __restrict__ h, float* __restrict__ out, int Dout) {
    int e = blockIdx.x;
    int s, d;
    float w;
    if (e < EE) {
        s = src[e];
        d = dst[e];
        w = g_norm[e];
    } else {
        s = e - EE;
        d = s;
        float di = g_dis[s];
        w = di * di;
    }
    const float4* hp = (const float4*)(h + (size_t)s * Dout);
    float* op = out + (size_t)d * Dout;
    int vecs = Dout >> 2;
    for (int v = threadIdx.x; v < vecs; v += blockDim.x) {
        float4 hv = hp[v];
        int f = v * 4;
        atomicAdd(op + f + 0, hv.x * w);
        atomicAdd(op + f + 1, hv.y * w);
        atomicAdd(op + f + 2, hv.z * w);
        atomicAdd(op + f + 3, hv.w * w);
    }
}

// ---------------- bias + relu (in place on g_act region) ----------------
__global__ void k_bias_relu(const float* __restrict__ b, float* __restrict__ a,
                            int Dout, int total) {
    int idx = blockIdx.x * blockDim.x + threadIdx.x;
    if (idx < total) {
        int f = idx % Dout;
        float v = a[idx] + b[f];
        a[idx] = fmaxf(v, 0.0f);
    }
}

// ---------------- mean pool ----------------
__global__ void k_pool(const int* __restrict__ batch, const float* __restrict__ a) {
    int idx = blockIdx.x * blockDim.x + threadIdx.x;
    if (idx < NN * 320) {
        int i = idx / 320;
        int f = idx - i * 320;
        int g = batch[i];
        atomicAdd(&g_pool[g * 320 + f], a[idx]);
        if (f == 0) atomicAdd(&g_cnt[g], 1.0f);
    }
}

__global__ void k_pooldiv() {
    int idx = blockIdx.x * blockDim.x + threadIdx.x;
    if (idx < GG * 320) {
        int g = idx / 320;
        g_pool[idx] /= fmaxf(g_cnt[g], 1.0f);
    }
}

// ---------------- small dense layer for the head: one block per graph row ----------------
__global__ __launch_bounds__(256) void k_dense(
    const float* __restrict__ A, const float* __restrict__ W,
    const float* __restrict__ b, float* __restrict__ C,
    int K, int Nout, int relu) {
    __shared__ float row[1024];
    int g = blockIdx.x;
    for (int k = threadIdx.x; k < K; k += blockDim.x) row[k] = A[g * K + k];
    __syncthreads();
    for (int n = threadIdx.x; n < Nout; n += blockDim.x) {
        float s = b[n];
        for (int k = 0; k < K; k++) s += row[k] * W[(size_t)k * Nout + n];
        if (relu) s = fmaxf(s, 0.0f);
        C[g * Nout + n] = s;
    }
}

__global__ void k_concat(const float* __restrict__ fp) {
    int idx = blockIdx.x * blockDim.x + threadIdx.x;
    if (idx < GG * 193) {
        int g = idx / 193;
        int f = idx - g * 193;
        g_cat[idx] = (f < FPD) ? fp[g * FPD + f] : g_t2[g * 128 + (f - FPD)];
    }
}

// ---------------- host driver ----------------
static void run_layer(const float* X, const float* W, const float* bias,
                      int K, int Dout, const int* src, const int* dst,
                      float* hbuf, float* actbuf) {
    dim3 grid(Dout / 64, (NN + 127) / 128);
    k_gemm<<<grid, 256>>>(X, W, hbuf, NN, K, Dout);
    cudaMemsetAsync(actbuf, 0, (size_t)NN * Dout * sizeof(float), 0);
    k_scatter<<<EE + NN, 128>>>(src, dst, hbuf, actbuf, Dout);
    int total = NN * Dout;
    k_bias_relu<<<(total + 255) / 256, 256>>>(bias, actbuf, Dout, total);
}

extern "C" void kernel_launch(void* const* d_in, const int* in_sizes, int n_in,
                              void* d_out, int out_size) {
    const float* x     = (const float*)d_in[0];
    const int*   ei    = (const int*)d_in[1];
    const int*   batch = (const int*)d_in[2];
    const float* fp    = (const float*)d_in[3];
    const float* W1 = (const float*)d_in[4];
    const float* b1 = (const float*)d_in[5];
    const float* W2 = (const float*)d_in[6];
    const float* b2 = (const float*)d_in[7];
    const float* W3 = (const float*)d_in[8];
    const float* b3 = (const float*)d_in[9];
    const float* Wg1 = (const float*)d_in[10];
    const float* bg1 = (const float*)d_in[11];
    const float* Wg2 = (const float*)d_in[12];
    const float* bg2 = (const float*)d_in[13];
    const float* Wf1 = (const float*)d_in[14];
    const float* bf1 = (const float*)d_in[15];
    const float* Wf2 = (const float*)d_in[16];
    const float* bf2 = (const float*)d_in[17];
    const float* Wo  = (const float*)d_in[18];
    const float* bo  = (const float*)d_in[19];
    float* out = (float*)d_out;

    const int* src = ei;
    const int* dst = ei + EE;

    float *hbuf, *actbuf, *degp, *poolp, *cntp, *t1p, *t2p, *catp, *t3p;
    cudaGetSymbolAddress((void**)&hbuf, g_h);
    cudaGetSymbolAddress((void**)&actbuf, g_act);
    cudaGetSymbolAddress((void**)&degp, g_deg);
    cudaGetSymbolAddress((void**)&poolp, g_pool);
    cudaGetSymbolAddress((void**)&cntp, g_cnt);
    cudaGetSymbolAddress((void**)&t1p, g_t1);
    cudaGetSymbolAddress((void**)&t2p, g_t2);
    cudaGetSymbolAddress((void**)&catp, g_cat);
    cudaGetSymbolAddress((void**)&t3p, g_t3);

    // degree / normalization coefficients
    cudaMemsetAsync(degp, 0, NN * sizeof(float), 0);
    k_deg<<<(EE + NN + 255) / 256, 256>>>(dst);
    k_dis<<<(NN + 255) / 256, 256>>>();
    k_norm<<<(EE + 255) / 256, 256>>>(src, dst);

    // three GCN layers
    run_layer(x,      W1, b1, DD,   DD,  src, dst, hbuf, actbuf);
    run_layer(actbuf, W2, b2, DD,   640, src, dst, hbuf, actbuf);
    run_layer(actbuf, W3, b3, 640,  320, src, dst, hbuf, actbuf);

    // global mean pool
    cudaMemsetAsync(poolp, 0, GG * 320 * sizeof(float), 0);
    cudaMemsetAsync(cntp, 0, GG * sizeof(float), 0);
    k_pool<<<(NN * 320 + 255) / 256, 256>>>(batch, actbuf);
    k_pooldiv<<<(GG * 320 + 255) / 256, 256>>>();

    // MLP head
    k_dense<<<GG, 256>>>(poolp, Wg1, bg1, t1p, 320, 1024, 1);
    k_dense<<<GG, 256>>>(t1p, Wg2, bg2, t2p, 1024, 128, 0);
    k_concat<<<(GG * 193 + 255) / 256, 256>>>(fp);
    k_dense<<<GG, 256>>>(catp, Wf1, bf1, t1p, 193, 1024, 1);
    k_dense<<<GG, 256>>>(t1p, Wf2, bf2, t3p, 1024, 512, 1);
    k_dense<<<GG, 256>>>(t3p, Wo, bo, out, 512, 1, 0);

    (void)in_sizes; (void)n_in; (void)out_size;
}

// round 3
// speedup vs baseline: 1.4827x; 1.4827x over previous
#include <cuda_runtime.h>

#define NN 20000
#define EE 320000
#define DD 1280
#define GG 64
#define FPD 65

// ---------------- scratch ----------------
__device__ float g_h[(size_t)NN * DD];    // GEMM output (pre-aggregation)
__device__ float g_act[(size_t)NN * DD];  // aggregated + activated features
__device__ float g_dis[NN];
__device__ int   g_ecnt[NN];
__device__ int   g_off[NN + 1];
__device__ int   g_cur[NN];
__device__ int   g_csrc[EE];
__device__ float g_cw[EE];
__device__ int   g_gcnt[GG];
__device__ int   g_goff[GG + 1];
__device__ float g_pool[GG * 320];
__device__ float g_t1[GG * 1024];
__device__ float g_t2[GG * 128];
__device__ float g_cat[GG * 193];
__device__ float g_t3[GG * 512];

// ---------------- CSR build ----------------
__global__ void k_count(const int* __restrict__ dst) {
    int i = blockIdx.x * blockDim.x + threadIdx.x;
    if (i < EE) atomicAdd(&g_ecnt[dst[i]], 1);
}

__global__ void k_dis() {
    int i = blockIdx.x * blockDim.x + threadIdx.x;
    if (i < NN) g_dis[i] = rsqrtf((float)(g_ecnt[i] + 1));  // +1 self loop, always >0
}

// single-block exclusive scan of g_ecnt -> g_off
__global__ __launch_bounds__(1024) void k_scan() {
    __shared__ int s[1024];
    __shared__ int carry_s;
    int t = threadIdx.x;
    if (t == 0) carry_s = 0;
    __syncthreads();
    for (int base = 0; base < NN; base += 1024) {
        int v = (base + t < NN) ? g_ecnt[base + t] : 0;
        s[t] = v;
        __syncthreads();
        for (int off = 1; off < 1024; off <<= 1) {
            int x = (t >= off) ? s[t - off] : 0;
            __syncthreads();
            s[t] += x;
            __syncthreads();
        }
        int carry = carry_s;
        if (base + t < NN) g_off[base + t] = carry + s[t] - v;
        __syncthreads();
        if (t == 0) carry_s = carry + s[1023];
        __syncthreads();
    }
    if (t == 0) g_off[NN] = carry_s;
}

__global__ void k_bucket(const int* __restrict__ src, const int* __restrict__ dst) {
    int e = blockIdx.x * blockDim.x + threadIdx.x;
    if (e < EE) {
        int d = dst[e];
        int s = src[e];
        int p = atomicAdd(&g_cur[d], 1);
        g_csrc[p] = s;
        g_cw[p] = g_dis[s] * g_dis[d];
    }
}

// ---------------- graph (batch) offsets for pooling ----------------
__global__ void k_gcnt(const int* __restrict__ batch) {
    int i = blockIdx.x * blockDim.x + threadIdx.x;
    if (i < NN) atomicAdd(&g_gcnt[batch[i]], 1);
}

__global__ void k_gscan() {
    if (threadIdx.x == 0) {
        int acc = 0;
        for (int g = 0; g < GG; g++) { g_goff[g] = acc; acc += g_gcnt[g]; }
        g_goff[GG] = acc;
    }
}

// ---------------- fp32 tiled GEMM: C[M,Nout] = A[M,K] @ B[K,Nout] ----------------
// BM=128, BN=128, BK=8, 256 threads, 8x8 per-thread (4+4 split quads)
__global__ __launch_bounds__(256) void k_gemm(
    const float* __restrict__ A, const float* __restrict__ B,
    float* __restrict__ C, int M, int K, int Nout) {
    __shared__ float As[8][132];
    __shared__ float Bs[8][128];

    int t = threadIdx.x;
    int m0 = blockIdx.y * 128;
    int n0 = blockIdx.x * 128;
    int tx = t & 15;
    int ty = t >> 4;

    float acc[8][8];
#pragma unroll
    for (int i = 0; i < 8; i++)
#pragma unroll
        for (int j = 0; j < 8; j++) acc[i][j] = 0.0f;

    // A-load coords: row = t>>1 (0..127), kk4 = (t&1)*4
    int a_row = t >> 1;
    int a_kk = (t & 1) * 4;
    // B-load coords: kk = t>>5 (0..7), col = (t&31)*4
    int b_kk = t >> 5;
    int b_col = (t & 31) * 4;

    for (int k0 = 0; k0 < K; k0 += 8) {
        float4 a4;
        if (m0 + a_row < M) {
            a4 = *(const float4*)&A[(size_t)(m0 + a_row) * K + k0 + a_kk];
        } else {
            a4 = make_float4(0.f, 0.f, 0.f, 0.f);
        }
        As[a_kk + 0][a_row] = a4.x;
        As[a_kk + 1][a_row] = a4.y;
        As[a_kk + 2][a_row] = a4.z;
        As[a_kk + 3][a_row] = a4.w;

        float4 b4;
        if (n0 + b_col < Nout) {
            b4 = *(const float4*)&B[(size_t)(k0 + b_kk) * Nout + n0 + b_col];
        } else {
            b4 = make_float4(0.f, 0.f, 0.f, 0.f);
        }
        *(float4*)&Bs[b_kk][b_col] = b4;

        __syncthreads();

#pragma unroll
        for (int kk = 0; kk < 8; kk++) {
            float ar[8], br[8];
#pragma unroll
            for (int i = 0; i < 4; i++) {
                ar[i] = As[kk][ty * 4 + i];
                ar[4 + i] = As[kk][64 + ty * 4 + i];
            }
            float4 b0 = *(float4*)&Bs[kk][tx * 4];
            float4 b1 = *(float4*)&Bs[kk][64 + tx * 4];
            br[0] = b0.x; br[1] = b0.y; br[2] = b0.z; br[3] = b0.w;
            br[4] = b1.x; br[5] = b1.y; br[6] = b1.z; br[7] = b1.w;
#pragma unroll
            for (int i = 0; i < 8; i++)
#pragma unroll
                for (int j = 0; j < 8; j++) acc[i][j] += ar[i] * br[j];
        }
        __syncthreads();
    }

#pragma unroll
    for (int i = 0; i < 8; i++) {
        int row = m0 + ((i < 4) ? (ty * 4 + i) : (64 + ty * 4 + i - 4));
        if (row < M) {
#pragma unroll
            for (int jh = 0; jh < 2; jh++) {
                int col = n0 + ((jh == 0) ? (tx * 4) : (64 + tx * 4));
                if (col < Nout) {
                    float4 c4 = make_float4(acc[i][jh * 4 + 0], acc[i][jh * 4 + 1],
                                            acc[i][jh * 4 + 2], acc[i][jh * 4 + 3]);
                    *(float4*)&C[(size_t)row * Nout + col] = c4;
                }
            }
        }
    }
}

// ---------------- CSR gather: out[d] = relu( sum_in h[s]*w + h[d]*dis[d]^2 + bias ) ----------------
// one block per node, blockDim = Dout/4 threads, one float4 per thread
__global__ void k_gather(const float* __restrict__ h, const float* __restrict__ bias,
                         float* __restrict__ out, int Dout) {
    int d = blockIdx.x;
    int f4 = threadIdx.x;
    int f = f4 * 4;

    float wd = g_dis[d];
    float selfw = wd * wd;
    const float4* hd = (const float4*)(h + (size_t)d * Dout);
    float4 hv = hd[f4];
    float4 acc = make_float4(hv.x * selfw, hv.y * selfw, hv.z * selfw, hv.w * selfw);

    int j = g_off[d];
    int jend = g_off[d + 1];
    for (; j + 1 < jend; j += 2) {
        int sa = g_csrc[j], sb = g_csrc[j + 1];
        float wa = g_cw[j], wb = g_cw[j + 1];
        float4 ha = ((const float4*)(h + (size_t)sa * Dout))[f4];
        float4 hb = ((const float4*)(h + (size_t)sb * Dout))[f4];
        acc.x += ha.x * wa + hb.x * wb;
        acc.y += ha.y * wa + hb.y * wb;
        acc.z += ha.z * wa + hb.z * wb;
        acc.w += ha.w * wa + hb.w * wb;
    }
    if (j < jend) {
        int sa = g_csrc[j];
        float wa = g_cw[j];
        float4 ha = ((const float4*)(h + (size_t)sa * Dout))[f4];
        acc.x += ha.x * wa;
        acc.y += ha.y * wa;
        acc.z += ha.z * wa;
        acc.w += ha.w * wa;
    }

    float4 bv = ((const float4*)bias)[f4];
    acc.x = fmaxf(acc.x + bv.x, 0.0f);
    acc.y = fmaxf(acc.y + bv.y, 0.0f);
    acc.z = fmaxf(acc.z + bv.z, 0.0f);
    acc.w = fmaxf(acc.w + bv.w, 0.0f);
    ((float4*)(out + (size_t)d * Dout))[f4] = acc;
}

// ---------------- mean pool: one block per graph, 320 threads ----------------
__global__ __launch_bounds__(320) void k_pool(const float* __restrict__ act) {
    int g = blockIdx.x;
    int f = threadIdx.x;
    int n0 = g_goff[g], n1 = g_goff[g + 1];
    float acc = 0.0f;
    for (int n = n0; n < n1; n++) acc += act[(size_t)n * 320 + f];
    float c = (float)(n1 - n0);
    g_pool[g * 320 + f] = acc / fmaxf(c, 1.0f);
}

// ---------------- small dense layer for the head ----------------
__global__ __launch_bounds__(256) void k_dense(
    const float* __restrict__ A, const float* __restrict__ W,
    const float* __restrict__ b, float* __restrict__ C,
    int K, int Nout, int relu) {
    __shared__ float row[1024];
    int g = blockIdx.x;
    for (int k = threadIdx.x; k < K; k += blockDim.x) row[k] = A[g * K + k];
    __syncthreads();
    for (int n = threadIdx.x; n < Nout; n += blockDim.x) {
        float s = b[n];
        for (int k = 0; k < K; k++) s += row[k] * W[(size_t)k * Nout + n];
        if (relu) s = fmaxf(s, 0.0f);
        C[g * Nout + n] = s;
    }
}

__global__ void k_concat(const float* __restrict__ fp) {
    int idx = blockIdx.x * blockDim.x + threadIdx.x;
    if (idx < GG * 193) {
        int g = idx / 193;
        int f = idx - g * 193;
        g_cat[idx] = (f < FPD) ? fp[g * FPD + f] : g_t2[g * 128 + (f - FPD)];
    }
}

// ---------------- host driver ----------------
static void run_layer(const float* X, const float* W, const float* bias,
                      int K, int Dout, float* hbuf, float* actbuf) {
    dim3 grid((Dout + 127) / 128, (NN + 127) / 128);
    k_gemm<<<grid, 256>>>(X, W, hbuf, NN, K, Dout);
    k_gather<<<NN, Dout / 4>>>(hbuf, bias, actbuf, Dout);
}

extern "C" void kernel_launch(void* const* d_in, const int* in_sizes, int n_in,
                              void* d_out, int out_size) {
    const float* x     = (const float*)d_in[0];
    const int*   ei    = (const int*)d_in[1];
    const int*   batch = (const int*)d_in[2];
    const float* fp    = (const float*)d_in[3];
    const float* W1 = (const float*)d_in[4];
    const float* b1 = (const float*)d_in[5];
    const float* W2 = (const float*)d_in[6];
    const float* b2 = (const float*)d_in[7];
    const float* W3 = (const float*)d_in[8];
    const float* b3 = (const float*)d_in[9];
    const float* Wg1 = (const float*)d_in[10];
    const float* bg1 = (const float*)d_in[11];
    const float* Wg2 = (const float*)d_in[12];
    const float* bg2 = (const float*)d_in[13];
    const float* Wf1 = (const float*)d_in[14];
    const float* bf1 = (const float*)d_in[15];
    const float* Wf2 = (const float*)d_in[16];
    const float* bf2 = (const float*)d_in[17];
    const float* Wo  = (const float*)d_in[18];
    const float* bo  = (const float*)d_in[19];
    float* out = (float*)d_out;

    const int* src = ei;
    const int* dst = ei + EE;

    float *hbuf, *actbuf, *poolp, *t1p, *t2p, *catp, *t3p;
    int *ecntp, *offp, *curp, *gcntp;
    cudaGetSymbolAddress((void**)&hbuf, g_h);
    cudaGetSymbolAddress((void**)&actbuf, g_act);
    cudaGetSymbolAddress((void**)&poolp, g_pool);
    cudaGetSymbolAddress((void**)&t1p, g_t1);
    cudaGetSymbolAddress((void**)&t2p, g_t2);
    cudaGetSymbolAddress((void**)&catp, g_cat);
    cudaGetSymbolAddress((void**)&t3p, g_t3);
    cudaGetSymbolAddress((void**)&ecntp, g_ecnt);
    cudaGetSymbolAddress((void**)&offp, g_off);
    cudaGetSymbolAddress((void**)&curp, g_cur);
    cudaGetSymbolAddress((void**)&gcntp, g_gcnt);

    // ---- CSR + norm build ----
    cudaMemsetAsync(ecntp, 0, NN * sizeof(int), 0);
    cudaMemsetAsync(gcntp, 0, GG * sizeof(int), 0);
    k_count<<<(EE + 255) / 256, 256>>>(dst);
    k_dis<<<(NN + 255) / 256, 256>>>();
    k_scan<<<1, 1024>>>();
    cudaMemcpyAsync(curp, offp, NN * sizeof(int), cudaMemcpyDeviceToDevice, 0);
    k_bucket<<<(EE + 255) / 256, 256>>>(src, dst);
    k_gcnt<<<(NN + 255) / 256, 256>>>(batch);
    k_gscan<<<1, 32>>>();

    // ---- three GCN layers ----
    run_layer(x,      W1, b1, DD,  DD,  hbuf, actbuf);
    run_layer(actbuf, W2, b2, DD,  640, hbuf, actbuf);
    run_layer(actbuf, W3, b3, 640, 320, hbuf, actbuf);

    // ---- global mean pool ----
    k_pool<<<GG, 320>>>(actbuf);

    // ---- MLP head ----
    k_dense<<<GG, 256>>>(poolp, Wg1, bg1, t1p, 320, 1024, 1);
    k_dense<<<GG, 256>>>(t1p, Wg2, bg2, t2p, 1024, 128, 0);
    k_concat<<<(GG * 193 + 255) / 256, 256>>>(fp);
    k_dense<<<GG, 256>>>(catp, Wf1, bf1, t1p, 193, 1024, 1);
    k_dense<<<GG, 256>>>(t1p, Wf2, bf2, t3p, 1024, 512, 1);
    k_dense<<<GG, 256>>>(t3p, Wo, bo, out, 512, 1, 0);

    (void)in_sizes; (void)n_in; (void)out_size;
}

// round 6
// speedup vs baseline: 2.4805x; 1.6729x over previous
#include <cuda_runtime.h>
#include <cstdint>

#define NN 20000
#define EE 320000
#define DD 1280
#define GG 64
#define FPD 65

// ======================= scratch =======================
__device__ float g_h[(size_t)NN * DD];
__device__ float g_act[(size_t)NN * DD];
__device__ float g_wt[(size_t)DD * DD];   // transposed weights [Nout][K]
__device__ float g_dis[NN];
__device__ int   g_ecnt[NN];
__device__ int   g_off[NN + 1];
__device__ int   g_cur[NN];
__device__ int   g_csrc[EE];
__device__ float g_cw[EE];
__device__ int   g_gcnt[GG];
__device__ int   g_goff[GG + 1];
__device__ float g_pool[GG * 320];
__device__ float g_t1[GG * 1024];
__device__ float g_t2[GG * 128];
__device__ float g_cat[GG * 193];
__device__ float g_t3[GG * 512];

// ======================= helpers =======================
__device__ __forceinline__ uint32_t f2tf32(float x) {
    uint32_t r;
    asm("cvt.rna.tf32.f32 %0, %1;" : "=r"(r) : "f"(x));
    return r;
}

__device__ __forceinline__ void mma_tf32(float* c, const uint32_t* a, const uint32_t* b) {
    asm volatile(
        "mma.sync.aligned.m16n8k8.row.col.f32.tf32.tf32.f32 "
        "{%0,%1,%2,%3}, {%4,%5,%6,%7}, {%8,%9}, {%0,%1,%2,%3};"
        : "+f"(c[0]), "+f"(c[1]), "+f"(c[2]), "+f"(c[3])
        : "r"(a[0]), "r"(a[1]), "r"(a[2]), "r"(a[3]), "r"(b[0]), "r"(b[1]));
}

// ======================= CSR build =======================
__global__ void k_count(const int* __restrict__ dst) {
    int i = blockIdx.x * blockDim.x + threadIdx.x;
    if (i < EE) atomicAdd(&g_ecnt[dst[i]], 1);
}

__global__ void k_dis() {
    int i = blockIdx.x * blockDim.x + threadIdx.x;
    if (i < NN) g_dis[i] = rsqrtf((float)(g_ecnt[i] + 1));
}

__global__ __launch_bounds__(1024) void k_scan() {
    __shared__ int s[1024];
    __shared__ int carry_s;
    int t = threadIdx.x;
    if (t == 0) carry_s = 0;
    __syncthreads();
    for (int base = 0; base < NN; base += 1024) {
        int v = (base + t < NN) ? g_ecnt[base + t] : 0;
        s[t] = v;
        __syncthreads();
        for (int off = 1; off < 1024; off <<= 1) {
            int x = (t >= off) ? s[t - off] : 0;
            __syncthreads();
            s[t] += x;
            __syncthreads();
        }
        int carry = carry_s;
        if (base + t < NN) g_off[base + t] = carry + s[t] - v;
        __syncthreads();
        if (t == 0) carry_s = carry + s[1023];
        __syncthreads();
    }
    if (t == 0) g_off[NN] = carry_s;
}

__global__ void k_bucket(const int* __restrict__ src, const int* __restrict__ dst) {
    int e = blockIdx.x * blockDim.x + threadIdx.x;
    if (e < EE) {
        int d = dst[e];
        int s = src[e];
        int p = atomicAdd(&g_cur[d], 1);
        g_csrc[p] = s;
        g_cw[p] = g_dis[s] * g_dis[d];
    }
}

__global__ void k_gcnt(const int* __restrict__ batch) {
    int i = blockIdx.x * blockDim.x + threadIdx.x;
    if (i < NN) atomicAdd(&g_gcnt[batch[i]], 1);
}

__global__ void k_gscan() {
    if (threadIdx.x == 0) {
        int acc = 0;
        for (int g = 0; g < GG; g++) { g_goff[g] = acc; acc += g_gcnt[g]; }
        g_goff[GG] = acc;
    }
}

// ======================= weight transpose: Wt[n][k] = W[k][n] =======================
__global__ __launch_bounds__(256) void k_transpose(const float* __restrict__ W,
                                                   float* __restrict__ Wt,
                                                   int K, int Nout) {
    __shared__ float tile[32][33];
    int kb = blockIdx.y * 32, nb = blockIdx.x * 32;
    int tx = threadIdx.x & 31, ty = threadIdx.x >> 5;  // 32x8
#pragma unroll
    for (int i = 0; i < 32; i += 8) {
        int kk = kb + ty + i, n = nb + tx;
        if (kk < K && n < Nout) tile[ty + i][tx] = W[(size_t)kk * Nout + n];
    }
    __syncthreads();
#pragma unroll
    for (int i = 0; i < 32; i += 8) {
        int n = nb + ty + i, kk = kb + tx;
        if (n < Nout && kk < K) Wt[(size_t)n * K + kk] = tile[tx][ty + i];
    }
}

// ======================= tf32 mma.sync GEMM =======================
// C[M,Nout] = A[M,K] @ Wt[Nout,K]^T.  BM=128, BN template (128/64), BK=16.
// 8 warps: warp_m = wid&3 (32 rows each), warp_n = wid>>2 (BN/2 cols each).
// smem pad 20: fragment reads (20*g + tig) mod 32 are conflict-free.
template <int BN>
__global__ __launch_bounds__(256) void k_gemm_mma(
    const float* __restrict__ A, const float* __restrict__ Bt,
    float* __restrict__ C, int M, int K, int Nout) {
    constexpr int NT = BN / 16;  // n8-tiles per warp (8 or 4)
    __shared__ float sA[128][20];
    __shared__ float sB[BN][20];

    int t = threadIdx.x;
    int wid = t >> 5, lane = t & 31;
    int grp = lane >> 2, tig = lane & 3;
    int warp_m = wid & 3, warp_n = wid >> 2;
    int m0 = blockIdx.y * 128, n0 = blockIdx.x * BN;

    float acc[2][NT][4];
#pragma unroll
    for (int mt = 0; mt < 2; mt++)
#pragma unroll
        for (int nt = 0; nt < NT; nt++)
#pragma unroll
            for (int i = 0; i < 4; i++) acc[mt][nt][i] = 0.0f;

    for (int k0 = 0; k0 < K; k0 += 16) {
        // load A 128x16: 512 float4 / 256 thr = 2 each
#pragma unroll
        for (int i = 0; i < 2; i++) {
            int v = t + i * 256;
            int row = v >> 2, c = (v & 3) * 4;
            float4 a4;
            if (m0 + row < M) {
                a4 = *(const float4*)&A[(size_t)(m0 + row) * K + k0 + c];
            } else {
                a4 = make_float4(0.f, 0.f, 0.f, 0.f);
            }
            sA[row][c + 0] = __uint_as_float(f2tf32(a4.x));
            sA[row][c + 1] = __uint_as_float(f2tf32(a4.y));
            sA[row][c + 2] = __uint_as_float(f2tf32(a4.z));
            sA[row][c + 3] = __uint_as_float(f2tf32(a4.w));
        }
        // load B BNx16: BN*4 float4
#pragma unroll
        for (int i = 0; i < BN / 64; i++) {
            int v = t + i * 256;
            int row = v >> 2, c = (v & 3) * 4;
            float4 b4 = *(const float4*)&Bt[(size_t)(n0 + row) * K + k0 + c];
            sB[row][c + 0] = __uint_as_float(f2tf32(b4.x));
            sB[row][c + 1] = __uint_as_float(f2tf32(b4.y));
            sB[row][c + 2] = __uint_as_float(f2tf32(b4.z));
            sB[row][c + 3] = __uint_as_float(f2tf32(b4.w));
        }
        __syncthreads();

#pragma unroll
        for (int ks = 0; ks < 2; ks++) {
            int kk = ks * 8;
            uint32_t af[2][4];
#pragma unroll
            for (int mt = 0; mt < 2; mt++) {
                int r = warp_m * 32 + mt * 16;
                af[mt][0] = __float_as_uint(sA[r + grp][kk + tig]);
                af[mt][1] = __float_as_uint(sA[r + grp + 8][kk + tig]);
                af[mt][2] = __float_as_uint(sA[r + grp][kk + tig + 4]);
                af[mt][3] = __float_as_uint(sA[r + grp + 8][kk + tig + 4]);
            }
#pragma unroll
            for (int nt = 0; nt < NT; nt++) {
                int c = warp_n * (NT * 8) + nt * 8;
                uint32_t bf[2];
                bf[0] = __float_as_uint(sB[c + grp][kk + tig]);
                bf[1] = __float_as_uint(sB[c + grp][kk + tig + 4]);
                mma_tf32(acc[0][nt], af[0], bf);
                mma_tf32(acc[1][nt], af[1], bf);
            }
        }
        __syncthreads();
    }

    // epilogue
#pragma unroll
    for (int mt = 0; mt < 2; mt++) {
        int r0 = m0 + warp_m * 32 + mt * 16 + grp;
#pragma unroll
        for (int nt = 0; nt < NT; nt++) {
            int col = n0 + warp_n * (NT * 8) + nt * 8 + tig * 2;
            if (r0 < M) {
                float2 v = make_float2(acc[mt][nt][0], acc[mt][nt][1]);
                *(float2*)&C[(size_t)r0 * Nout + col] = v;
            }
            if (r0 + 8 < M) {
                float2 v = make_float2(acc[mt][nt][2], acc[mt][nt][3]);
                *(float2*)&C[(size_t)(r0 + 8) * Nout + col] = v;
            }
        }
    }
}

// ======================= CSR gather + bias + relu =======================
__global__ void k_gather(const float* __restrict__ h, const float* __restrict__ bias,
                         float* __restrict__ out, int Dout) {
    int d = blockIdx.x;
    int f4 = threadIdx.x;

    float wd = g_dis[d];
    float selfw = wd * wd;
    float4 hv = ((const float4*)(h + (size_t)d * Dout))[f4];
    float4 acc = make_float4(hv.x * selfw, hv.y * selfw, hv.z * selfw, hv.w * selfw);

    int j = g_off[d];
    int jend = g_off[d + 1];
    for (; j + 1 < jend; j += 2) {
        int sa = g_csrc[j], sb = g_csrc[j + 1];
        float wa = g_cw[j], wb = g_cw[j + 1];
        float4 ha = ((const float4*)(h + (size_t)sa * Dout))[f4];
        float4 hb = ((const float4*)(h + (size_t)sb * Dout))[f4];
        acc.x += ha.x * wa + hb.x * wb;
        acc.y += ha.y * wa + hb.y * wb;
        acc.z += ha.z * wa + hb.z * wb;
        acc.w += ha.w * wa + hb.w * wb;
    }
    if (j < jend) {
        int sa = g_csrc[j];
        float wa = g_cw[j];
        float4 ha = ((const float4*)(h + (size_t)sa * Dout))[f4];
        acc.x += ha.x * wa;
        acc.y += ha.y * wa;
        acc.z += ha.z * wa;
        acc.w += ha.w * wa;
    }

    float4 bv = ((const float4*)bias)[f4];
    acc.x = fmaxf(acc.x + bv.x, 0.0f);
    acc.y = fmaxf(acc.y + bv.y, 0.0f);
    acc.z = fmaxf(acc.z + bv.z, 0.0f);
    acc.w = fmaxf(acc.w + bv.w, 0.0f);
    ((float4*)(out + (size_t)d * Dout))[f4] = acc;
}

// ======================= pool + head =======================
__global__ __launch_bounds__(320) void k_pool(const float* __restrict__ act) {
    int g = blockIdx.x;
    int f = threadIdx.x;
    int n0 = g_goff[g], n1 = g_goff[g + 1];
    float acc = 0.0f;
    for (int n = n0; n < n1; n++) acc += act[(size_t)n * 320 + f];
    float c = (float)(n1 - n0);
    g_pool[g * 320 + f] = acc / fmaxf(c, 1.0f);
}

__global__ __launch_bounds__(256) void k_dense(
    const float* __restrict__ A, const float* __restrict__ W,
    const float* __restrict__ b, float* __restrict__ C,
    int K, int Nout, int relu) {
    __shared__ float row[1024];
    int g = blockIdx.x;
    for (int k = threadIdx.x; k < K; k += blockDim.x) row[k] = A[g * K + k];
    __syncthreads();
    for (int n = threadIdx.x; n < Nout; n += blockDim.x) {
        float s = b[n];
        for (int k = 0; k < K; k++) s += row[k] * W[(size_t)k * Nout + n];
        if (relu) s = fmaxf(s, 0.0f);
        C[g * Nout + n] = s;
    }
}

__global__ void k_concat(const float* __restrict__ fp) {
    int idx = blockIdx.x * blockDim.x + threadIdx.x;
    if (idx < GG * 193) {
        int g = idx / 193;
        int f = idx - g * 193;
        g_cat[idx] = (f < FPD) ? fp[g * FPD + f] : g_t2[g * 128 + (f - FPD)];
    }
}

// ======================= host driver =======================
static void run_layer(const float* X, const float* W, const float* bias,
                      int K, int Dout, float* hbuf, float* actbuf, float* wtp) {
    dim3 tgrid(Dout / 32, K / 32);
    k_transpose<<<tgrid, 256>>>(W, wtp, K, Dout);
    if (Dout % 128 == 0) {
        dim3 grid(Dout / 128, (NN + 127) / 128);
        k_gemm_mma<128><<<grid, 256>>>(X, wtp, hbuf, NN, K, Dout);
    } else {
        dim3 grid(Dout / 64, (NN + 127) / 128);
        k_gemm_mma<64><<<grid, 256>>>(X, wtp, hbuf, NN, K, Dout);
    }
    k_gather<<<NN, Dout / 4>>>(hbuf, bias, actbuf, Dout);
}

extern "C" void kernel_launch(void* const* d_in, const int* in_sizes, int n_in,
                              void* d_out, int out_size) {
    const float* x     = (const float*)d_in[0];
    const int*   ei    = (const int*)d_in[1];
    const int*   batch = (const int*)d_in[2];
    const float* fp    = (const float*)d_in[3];
    const float* W1 = (const float*)d_in[4];
    const float* b1 = (const float*)d_in[5];
    const float* W2 = (const float*)d_in[6];
    const float* b2 = (const float*)d_in[7];
    const float* W3 = (const float*)d_in[8];
    const float* b3 = (const float*)d_in[9];
    const float* Wg1 = (const float*)d_in[10];
    const float* bg1 = (const float*)d_in[11];
    const float* Wg2 = (const float*)d_in[12];
    const float* bg2 = (const float*)d_in[13];
    const float* Wf1 = (const float*)d_in[14];
    const float* bf1 = (const float*)d_in[15];
    const float* Wf2 = (const float*)d_in[16];
    const float* bf2 = (const float*)d_in[17];
    const float* Wo  = (const float*)d_in[18];
    const float* bo  = (const float*)d_in[19];
    float* out = (float*)d_out;

    const int* src = ei;
    const int* dst = ei + EE;

    float *hbuf, *actbuf, *wtp, *poolp, *t1p, *t2p, *catp, *t3p;
    int *ecntp, *offp, *curp, *gcntp;
    cudaGetSymbolAddress((void**)&hbuf, g_h);
    cudaGetSymbolAddress((void**)&actbuf, g_act);
    cudaGetSymbolAddress((void**)&wtp, g_wt);
    cudaGetSymbolAddress((void**)&poolp, g_pool);
    cudaGetSymbolAddress((void**)&t1p, g_t1);
    cudaGetSymbolAddress((void**)&t2p, g_t2);
    cudaGetSymbolAddress((void**)&catp, g_cat);
    cudaGetSymbolAddress((void**)&t3p, g_t3);
    cudaGetSymbolAddress((void**)&ecntp, g_ecnt);
    cudaGetSymbolAddress((void**)&offp, g_off);
    cudaGetSymbolAddress((void**)&curp, g_cur);
    cudaGetSymbolAddress((void**)&gcntp, g_gcnt);

    // ---- CSR + norm build ----
    cudaMemsetAsync(ecntp, 0, NN * sizeof(int), 0);
    cudaMemsetAsync(gcntp, 0, GG * sizeof(int), 0);
    k_count<<<(EE + 255) / 256, 256>>>(dst);
    k_dis<<<(NN + 255) / 256, 256>>>();
    k_scan<<<1, 1024>>>();
    cudaMemcpyAsync(curp, offp, NN * sizeof(int), cudaMemcpyDeviceToDevice, 0);
    k_bucket<<<(EE + 255) / 256, 256>>>(src, dst);
    k_gcnt<<<(NN + 255) / 256, 256>>>(batch);
    k_gscan<<<1, 32>>>();

    // ---- three GCN layers (tf32 mma.sync GEMMs) ----
    run_layer(x,      W1, b1, DD,  DD,  hbuf, actbuf, wtp);
    run_layer(actbuf, W2, b2, DD,  640, hbuf, actbuf, wtp);
    run_layer(actbuf, W3, b3, 640, 320, hbuf, actbuf, wtp);

    // ---- global mean pool ----
    k_pool<<<GG, 320>>>(actbuf);

    // ---- MLP head ----
    k_dense<<<GG, 256>>>(poolp, Wg1, bg1, t1p, 320, 1024, 1);
    k_dense<<<GG, 256>>>(t1p, Wg2, bg2, t2p, 1024, 128, 0);
    k_concat<<<(GG * 193 + 255) / 256, 256>>>(fp);
    k_dense<<<GG, 256>>>(catp, Wf1, bf1, t1p, 193, 1024, 1);
    k_dense<<<GG, 256>>>(t1p, Wf2, bf2, t3p, 1024, 512, 1);
    k_dense<<<GG, 256>>>(t3p, Wo, bo, out, 512, 1, 0);

    (void)in_sizes; (void)n_in; (void)out_size;
}

// round 8
// speedup vs baseline: 3.0616x; 1.2342x over previous
#include <cuda_runtime.h>
#include <cstdint>

#define NN 20000
#define EE 320000
#define DD 1280
#define GG 64
#define FPD 65

// ======================= scratch =======================
__device__ float g_h[(size_t)NN * DD];
__device__ float g_act[(size_t)NN * DD];
__device__ float g_wt[(size_t)DD * DD];   // transposed weights [Nout][K]
__device__ float g_dis[NN];
__device__ int   g_ecnt[NN];
__device__ int   g_off[NN + 1];
__device__ int   g_cur[NN];
__device__ int   g_csrc[EE];
__device__ float g_cw[EE];
__device__ int   g_gcnt[GG];
__device__ int   g_goff[GG + 1];
__device__ float g_pool[GG * 320];
__device__ float g_t1[GG * 1024];
__device__ float g_t2[GG * 128];
__device__ float g_cat[GG * 193];
__device__ float g_t3[GG * 512];

// ======================= helpers =======================
__device__ __forceinline__ uint32_t smem_u32(const void* p) {
    uint32_t a;
    asm("{ .reg .u64 tmp; cvta.to.shared.u64 tmp, %1; cvt.u32.u64 %0, tmp; }"
        : "=r"(a) : "l"(p));
    return a;
}

__device__ __forceinline__ void cp_async16(uint32_t saddr, const void* gptr, int src_bytes) {
    asm volatile("cp.async.cg.shared.global [%0], [%1], 16, %2;"
                 :: "r"(saddr), "l"(gptr), "r"(src_bytes));
}
#define CP_COMMIT() asm volatile("cp.async.commit_group;" ::: "memory")
#define CP_WAIT1()  asm volatile("cp.async.wait_group 1;" ::: "memory")

__device__ __forceinline__ void mma_tf32(float* c, const uint32_t* a, const uint32_t* b) {
    asm volatile(
        "mma.sync.aligned.m16n8k8.row.col.f32.tf32.tf32.f32 "
        "{%0,%1,%2,%3}, {%4,%5,%6,%7}, {%8,%9}, {%0,%1,%2,%3};"
        : "+f"(c[0]), "+f"(c[1]), "+f"(c[2]), "+f"(c[3])
        : "r"(a[0]), "r"(a[1]), "r"(a[2]), "r"(a[3]), "r"(b[0]), "r"(b[1]));
}

// ======================= CSR build =======================
__global__ void k_count(const int* __restrict__ dst) {
    int i = blockIdx.x * blockDim.x + threadIdx.x;
    if (i < EE) atomicAdd(&g_ecnt[dst[i]], 1);
}

__global__ void k_dis() {
    int i = blockIdx.x * blockDim.x + threadIdx.x;
    if (i < NN) g_dis[i] = rsqrtf((float)(g_ecnt[i] + 1));
}

__global__ __launch_bounds__(1024) void k_scan() {
    __shared__ int s[1024];
    __shared__ int carry_s;
    int t = threadIdx.x;
    if (t == 0) carry_s = 0;
    __syncthreads();
    for (int base = 0; base < NN; base += 1024) {
        int v = (base + t < NN) ? g_ecnt[base + t] : 0;
        s[t] = v;
        __syncthreads();
        for (int off = 1; off < 1024; off <<= 1) {
            int x = (t >= off) ? s[t - off] : 0;
            __syncthreads();
            s[t] += x;
            __syncthreads();
        }
        int carry = carry_s;
        if (base + t < NN) g_off[base + t] = carry + s[t] - v;
        __syncthreads();
        if (t == 0) carry_s = carry + s[1023];
        __syncthreads();
    }
    if (t == 0) g_off[NN] = carry_s;
}

__global__ void k_bucket(const int* __restrict__ src, const int* __restrict__ dst) {
    int e = blockIdx.x * blockDim.x + threadIdx.x;
    if (e < EE) {
        int d = dst[e];
        int s = src[e];
        int p = atomicAdd(&g_cur[d], 1);
        g_csrc[p] = s;
        g_cw[p] = g_dis[s] * g_dis[d];
    }
}

__global__ void k_gcnt(const int* __restrict__ batch) {
    int i = blockIdx.x * blockDim.x + threadIdx.x;
    if (i < NN) atomicAdd(&g_gcnt[batch[i]], 1);
}

__global__ void k_gscan() {
    if (threadIdx.x == 0) {
        int acc = 0;
        for (int g = 0; g < GG; g++) { g_goff[g] = acc; acc += g_gcnt[g]; }
        g_goff[GG] = acc;
    }
}

// ======================= weight transpose: Wt[n][k] = W[k][n] =======================
__global__ __launch_bounds__(256) void k_transpose(const float* __restrict__ W,
                                                   float* __restrict__ Wt,
                                                   int K, int Nout) {
    __shared__ float tile[32][33];
    int kb = blockIdx.y * 32, nb = blockIdx.x * 32;
    int tx = threadIdx.x & 31, ty = threadIdx.x >> 5;  // 32x8
#pragma unroll
    for (int i = 0; i < 32; i += 8) {
        int kk = kb + ty + i, n = nb + tx;
        if (kk < K && n < Nout) tile[ty + i][tx] = W[(size_t)kk * Nout + n];
    }
    __syncthreads();
#pragma unroll
    for (int i = 0; i < 32; i += 8) {
        int n = nb + ty + i, kk = kb + tx;
        if (n < Nout && kk < K) Wt[(size_t)n * K + kk] = tile[tx][ty + i];
    }
}

// ======================= tf32 mma.sync GEMM, cp.async double-buffered =======================
// C[M,Nout] = A[M,K] @ Wt[Nout,K]^T.  BM=128, BN template (128/64), BK=32.
// 8 warps: warp_m = wid&3 (32 rows), warp_n = wid>>2 (BN/2 cols).
// Row stride 36 floats: conflict-free fragment reads, 16B-aligned cp.async dst.
template <int BN>
__global__ __launch_bounds__(256) void k_gemm_mma(
    const float* __restrict__ A, const float* __restrict__ Bt,
    float* __restrict__ C, int M, int K, int Nout) {
    constexpr int NT = BN / 16;  // n8-tiles per warp
    __shared__ float sA[2][128][36];
    __shared__ float sB[2][BN][36];

    int t = threadIdx.x;
    int wid = t >> 5, lane = t & 31;
    int grp = lane >> 2, tig = lane & 3;
    int warp_m = wid & 3, warp_n = wid >> 2;
    int m0 = blockIdx.y * 128, n0 = blockIdx.x * BN;

    uint32_t aA = smem_u32(sA);
    uint32_t aB = smem_u32(sB);

    float acc[2][NT][4];
#pragma unroll
    for (int mt = 0; mt < 2; mt++)
#pragma unroll
        for (int nt = 0; nt < NT; nt++)
#pragma unroll
            for (int i = 0; i < 4; i++) acc[mt][nt][i] = 0.0f;

    int nk = K >> 5;

    auto load_tiles = [&](int buf, int k0) {
        // A tile: 128x32 floats = 1024 float4, 4 per thread
#pragma unroll
        for (int i = 0; i < 4; i++) {
            int v = t + i * 256;
            int row = v >> 3, c4 = (v & 7) * 4;
            int grow = m0 + row;
            const float* src = &A[(size_t)((grow < M) ? grow : 0) * K + k0 + c4];
            int sz = (grow < M) ? 16 : 0;
            cp_async16(aA + (uint32_t)(((buf * 128 + row) * 36 + c4) * 4), src, sz);
        }
        // B tile: BNx32 floats = BN/32 * 256 float4
#pragma unroll
        for (int i = 0; i < BN / 32; i++) {
            int v = t + i * 256;
            int row = v >> 3, c4 = (v & 7) * 4;
            const float* src = &Bt[(size_t)(n0 + row) * K + k0 + c4];
            cp_async16(aB + (uint32_t)(((buf * BN + row) * 36 + c4) * 4), src, 16);
        }
    };

    load_tiles(0, 0);
    CP_COMMIT();

    for (int kt = 0; kt < nk; kt++) {
        int buf = kt & 1;
        if (kt + 1 < nk) load_tiles(buf ^ 1, (kt + 1) << 5);
        CP_COMMIT();
        CP_WAIT1();
        __syncthreads();

#pragma unroll
        for (int ks = 0; ks < 4; ks++) {
            int kk = ks * 8;
            uint32_t af[2][4];
#pragma unroll
            for (int mt = 0; mt < 2; mt++) {
                int r = warp_m * 32 + mt * 16;
                af[mt][0] = __float_as_uint(sA[buf][r + grp][kk + tig]);
                af[mt][1] = __float_as_uint(sA[buf][r + grp + 8][kk + tig]);
                af[mt][2] = __float_as_uint(sA[buf][r + grp][kk + tig + 4]);
                af[mt][3] = __float_as_uint(sA[buf][r + grp + 8][kk + tig + 4]);
            }
#pragma unroll
            for (int nt = 0; nt < NT; nt++) {
                int c = warp_n * (NT * 8) + nt * 8;
                uint32_t bf[2];
                bf[0] = __float_as_uint(sB[buf][c + grp][kk + tig]);
                bf[1] = __float_as_uint(sB[buf][c + grp][kk + tig + 4]);
                mma_tf32(acc[0][nt], af[0], bf);
                mma_tf32(acc[1][nt], af[1], bf);
            }
        }
        __syncthreads();
    }

    // epilogue
#pragma unroll
    for (int mt = 0; mt < 2; mt++) {
        int r0 = m0 + warp_m * 32 + mt * 16 + grp;
#pragma unroll
        for (int nt = 0; nt < NT; nt++) {
            int col = n0 + warp_n * (NT * 8) + nt * 8 + tig * 2;
            if (r0 < M) {
                float2 v = make_float2(acc[mt][nt][0], acc[mt][nt][1]);
                *(float2*)&C[(size_t)r0 * Nout + col] = v;
            }
            if (r0 + 8 < M) {
                float2 v = make_float2(acc[mt][nt][2], acc[mt][nt][3]);
                *(float2*)&C[(size_t)(r0 + 8) * Nout + col] = v;
            }
        }
    }
}

// ======================= CSR gather + bias + relu =======================
__global__ void k_gather(const float* __restrict__ h, const float* __restrict__ bias,
                         float* __restrict__ out, int Dout) {
    int d = blockIdx.x;
    int f4 = threadIdx.x;

    float wd = g_dis[d];
    float selfw = wd * wd;
    float4 hv = ((const float4*)(h + (size_t)d * Dout))[f4];
    float4 acc = make_float4(hv.x * selfw, hv.y * selfw, hv.z * selfw, hv.w * selfw);

    int j = g_off[d];
    int jend = g_off[d + 1];
    for (; j + 1 < jend; j += 2) {
        int sa = g_csrc[j], sb = g_csrc[j + 1];
        float wa = g_cw[j], wb = g_cw[j + 1];
        float4 ha = ((const float4*)(h + (size_t)sa * Dout))[f4];
        float4 hb = ((const float4*)(h + (size_t)sb * Dout))[f4];
        acc.x += ha.x * wa + hb.x * wb;
        acc.y += ha.y * wa + hb.y * wb;
        acc.z += ha.z * wa + hb.z * wb;
        acc.w += ha.w * wa + hb.w * wb;
    }
    if (j < jend) {
        int sa = g_csrc[j];
        float wa = g_cw[j];
        float4 ha = ((const float4*)(h + (size_t)sa * Dout))[f4];
        acc.x += ha.x * wa;
        acc.y += ha.y * wa;
        acc.z += ha.z * wa;
        acc.w += ha.w * wa;
    }

    float4 bv = ((const float4*)bias)[f4];
    acc.x = fmaxf(acc.x + bv.x, 0.0f);
    acc.y = fmaxf(acc.y + bv.y, 0.0f);
    acc.z = fmaxf(acc.z + bv.z, 0.0f);
    acc.w = fmaxf(acc.w + bv.w, 0.0f);
    ((float4*)(out + (size_t)d * Dout))[f4] = acc;
}

// ======================= pool + head =======================
__global__ __launch_bounds__(320) void k_pool(const float* __restrict__ act) {
    int g = blockIdx.x;
    int f = threadIdx.x;
    int n0 = g_goff[g], n1 = g_goff[g + 1];
    float acc = 0.0f;
    for (int n = n0; n < n1; n++) acc += act[(size_t)n * 320 + f];
    float c = (float)(n1 - n0);
    g_pool[g * 320 + f] = acc / fmaxf(c, 1.0f);
}

__global__ __launch_bounds__(256) void k_dense(
    const float* __restrict__ A, const float* __restrict__ W,
    const float* __restrict__ b, float* __restrict__ C,
    int K, int Nout, int relu) {
    __shared__ float row[1024];
    int g = blockIdx.x;
    for (int k = threadIdx.x; k < K; k += blockDim.x) row[k] = A[g * K + k];
    __syncthreads();
    for (int n = threadIdx.x; n < Nout; n += blockDim.x) {
        float s = b[n];
        for (int k = 0; k < K; k++) s += row[k] * W[(size_t)k * Nout + n];
        if (relu) s = fmaxf(s, 0.0f);
        C[g * Nout + n] = s;
    }
}

__global__ void k_concat(const float* __restrict__ fp) {
    int idx = blockIdx.x * blockDim.x + threadIdx.x;
    if (idx < GG * 193) {
        int g = idx / 193;
        int f = idx - g * 193;
        g_cat[idx] = (f < FPD) ? fp[g * FPD + f] : g_t2[g * 128 + (f - FPD)];
    }
}

// ======================= host driver =======================
static void run_layer(const float* X, const float* W, const float* bias,
                      int K, int Dout, float* hbuf, float* actbuf, float* wtp) {
    dim3 tgrid(Dout / 32, K / 32);
    k_transpose<<<tgrid, 256>>>(W, wtp, K, Dout);
    if (Dout % 128 == 0) {
        dim3 grid(Dout / 128, (NN + 127) / 128);
        k_gemm_mma<128><<<grid, 256>>>(X, wtp, hbuf, NN, K, Dout);
    } else {
        dim3 grid(Dout / 64, (NN + 127) / 128);
        k_gemm_mma<64><<<grid, 256>>>(X, wtp, hbuf, NN, K, Dout);
    }
    k_gather<<<NN, Dout / 4>>>(hbuf, bias, actbuf, Dout);
}

extern "C" void kernel_launch(void* const* d_in, const int* in_sizes, int n_in,
                              void* d_out, int out_size) {
    const float* x     = (const float*)d_in[0];
    const int*   ei    = (const int*)d_in[1];
    const int*   batch = (const int*)d_in[2];
    const float* fp    = (const float*)d_in[3];
    const float* W1 = (const float*)d_in[4];
    const float* b1 = (const float*)d_in[5];
    const float* W2 = (const float*)d_in[6];
    const float* b2 = (const float*)d_in[7];
    const float* W3 = (const float*)d_in[8];
    const float* b3 = (const float*)d_in[9];
    const float* Wg1 = (const float*)d_in[10];
    const float* bg1 = (const float*)d_in[11];
    const float* Wg2 = (const float*)d_in[12];
    const float* bg2 = (const float*)d_in[13];
    const float* Wf1 = (const float*)d_in[14];
    const float* bf1 = (const float*)d_in[15];
    const float* Wf2 = (const float*)d_in[16];
    const float* bf2 = (const float*)d_in[17];
    const float* Wo  = (const float*)d_in[18];
    const float* bo  = (const float*)d_in[19];
    float* out = (float*)d_out;

    const int* src = ei;
    const int* dst = ei + EE;

    float *hbuf, *actbuf, *wtp, *poolp, *t1p, *t2p, *catp, *t3p;
    int *ecntp, *offp, *curp, *gcntp;
    cudaGetSymbolAddress((void**)&hbuf, g_h);
    cudaGetSymbolAddress((void**)&actbuf, g_act);
    cudaGetSymbolAddress((void**)&wtp, g_wt);
    cudaGetSymbolAddress((void**)&poolp, g_pool);
    cudaGetSymbolAddress((void**)&t1p, g_t1);
    cudaGetSymbolAddress((void**)&t2p, g_t2);
    cudaGetSymbolAddress((void**)&catp, g_cat);
    cudaGetSymbolAddress((void**)&t3p, g_t3);
    cudaGetSymbolAddress((void**)&ecntp, g_ecnt);
    cudaGetSymbolAddress((void**)&offp, g_off);
    cudaGetSymbolAddress((void**)&curp, g_cur);
    cudaGetSymbolAddress((void**)&gcntp, g_gcnt);

    // ---- CSR + norm build ----
    cudaMemsetAsync(ecntp, 0, NN * sizeof(int), 0);
    cudaMemsetAsync(gcntp, 0, GG * sizeof(int), 0);
    k_count<<<(EE + 255) / 256, 256>>>(dst);
    k_dis<<<(NN + 255) / 256, 256>>>();
    k_scan<<<1, 1024>>>();
    cudaMemcpyAsync(curp, offp, NN * sizeof(int), cudaMemcpyDeviceToDevice, 0);
    k_bucket<<<(EE + 255) / 256, 256>>>(src, dst);
    k_gcnt<<<(NN + 255) / 256, 256>>>(batch);
    k_gscan<<<1, 32>>>();

    // ---- three GCN layers (tf32 mma.sync GEMMs, cp.async pipelined) ----
    run_layer(x,      W1, b1, DD,  DD,  hbuf, actbuf, wtp);
    run_layer(actbuf, W2, b2, DD,  640, hbuf, actbuf, wtp);
    run_layer(actbuf, W3, b3, 640, 320, hbuf, actbuf, wtp);

    // ---- global mean pool ----
    k_pool<<<GG, 320>>>(actbuf);

    // ---- MLP head ----
    k_dense<<<GG, 256>>>(poolp, Wg1, bg1, t1p, 320, 1024, 1);
    k_dense<<<GG, 256>>>(t1p, Wg2, bg2, t2p, 1024, 128, 0);
    k_concat<<<(GG * 193 + 255) / 256, 256>>>(fp);
    k_dense<<<GG, 256>>>(catp, Wf1, bf1, t1p, 193, 1024, 1);
    k_dense<<<GG, 256>>>(t1p, Wf2, bf2, t3p, 1024, 512, 1);
    k_dense<<<GG, 256>>>(t3p, Wo, bo, out, 512, 1, 0);

    (void)in_sizes; (void)n_in; (void)out_size;
}

// round 11
// speedup vs baseline: 3.1608x; 1.0324x over previous
#include <cuda_runtime.h>
#include <cuda_fp16.h>
#include <cstdint>

#define NN 20000
#define EE 320000
#define DD 1280
#define GG 64
#define FPD 65

// ======================= scratch =======================
__device__ __half g_h[(size_t)NN * DD];   // GEMM output (fp16 container)
__device__ float g_act[(size_t)NN * DD];  // aggregated + activated (fp32)
__device__ float g_wt[(size_t)DD * DD];   // transposed weights [Nout][K]
__device__ float g_dis[NN];
__device__ int   g_ecnt[NN];
__device__ int   g_off[NN + 1];
__device__ int   g_cur[NN];
__device__ int   g_csrc[EE];
__device__ float g_cw[EE];
__device__ int   g_gcnt[GG];
__device__ int   g_goff[GG + 1];
__device__ float g_pool[GG * 320];
__device__ float g_t1[GG * 1024];
__device__ float g_t2[GG * 128];
__device__ float g_cat[GG * 193];
__device__ float g_t3[GG * 512];

// ======================= helpers =======================
__device__ __forceinline__ uint32_t smem_u32(const void* p) {
    uint32_t a;
    asm("{ .reg .u64 tmp; cvta.to.shared.u64 tmp, %1; cvt.u32.u64 %0, tmp; }"
        : "=r"(a) : "l"(p));
    return a;
}

__device__ __forceinline__ void cp_async16(uint32_t saddr, const void* gptr, int src_bytes) {
    asm volatile("cp.async.cg.shared.global [%0], [%1], 16, %2;"
                 :: "r"(saddr), "l"(gptr), "r"(src_bytes));
}
#define CP_COMMIT() asm volatile("cp.async.commit_group;" ::: "memory")
#define CP_WAIT1()  asm volatile("cp.async.wait_group 1;" ::: "memory")

__device__ __forceinline__ void mma_tf32(float* c, const uint32_t* a, const uint32_t* b) {
    asm volatile(
        "mma.sync.aligned.m16n8k8.row.col.f32.tf32.tf32.f32 "
        "{%0,%1,%2,%3}, {%4,%5,%6,%7}, {%8,%9}, {%0,%1,%2,%3};"
        : "+f"(c[0]), "+f"(c[1]), "+f"(c[2]), "+f"(c[3])
        : "r"(a[0]), "r"(a[1]), "r"(a[2]), "r"(a[3]), "r"(b[0]), "r"(b[1]));
}

// ======================= CSR build =======================
__global__ void k_count(const int* __restrict__ dst) {
    int i = blockIdx.x * blockDim.x + threadIdx.x;
    if (i < EE) atomicAdd(&g_ecnt[dst[i]], 1);
}

__global__ void k_dis() {
    int i = blockIdx.x * blockDim.x + threadIdx.x;
    if (i < NN) g_dis[i] = rsqrtf((float)(g_ecnt[i] + 1));
}

__global__ __launch_bounds__(1024) void k_scan() {
    __shared__ int s[1024];
    __shared__ int carry_s;
    int t = threadIdx.x;
    if (t == 0) carry_s = 0;
    __syncthreads();
    for (int base = 0; base < NN; base += 1024) {
        int v = (base + t < NN) ? g_ecnt[base + t] : 0;
        s[t] = v;
        __syncthreads();
        for (int off = 1; off < 1024; off <<= 1) {
            int x = (t >= off) ? s[t - off] : 0;
            __syncthreads();
            s[t] += x;
            __syncthreads();
        }
        int carry = carry_s;
        if (base + t < NN) g_off[base + t] = carry + s[t] - v;
        __syncthreads();
        if (t == 0) carry_s = carry + s[1023];
        __syncthreads();
    }
    if (t == 0) g_off[NN] = carry_s;
}

__global__ void k_bucket(const int* __restrict__ src, const int* __restrict__ dst) {
    int e = blockIdx.x * blockDim.x + threadIdx.x;
    if (e < EE) {
        int d = dst[e];
        int s = src[e];
        int p = atomicAdd(&g_cur[d], 1);
        g_csrc[p] = s;
        g_cw[p] = g_dis[s] * g_dis[d];
    }
}

__global__ void k_gcnt(const int* __restrict__ batch) {
    int i = blockIdx.x * blockDim.x + threadIdx.x;
    if (i < NN) atomicAdd(&g_gcnt[batch[i]], 1);
}

__global__ void k_gscan() {
    if (threadIdx.x == 0) {
        int acc = 0;
        for (int g = 0; g < GG; g++) { g_goff[g] = acc; acc += g_gcnt[g]; }
        g_goff[GG] = acc;
    }
}

// ======================= weight transpose: Wt[n][k] = W[k][n] =======================
__global__ __launch_bounds__(256) void k_transpose(const float* __restrict__ W,
                                                   float* __restrict__ Wt,
                                                   int K, int Nout) {
    __shared__ float tile[32][33];
    int kb = blockIdx.y * 32, nb = blockIdx.x * 32;
    int tx = threadIdx.x & 31, ty = threadIdx.x >> 5;  // 32x8
#pragma unroll
    for (int i = 0; i < 32; i += 8) {
        int kk = kb + ty + i, n = nb + tx;
        if (kk < K && n < Nout) tile[ty + i][tx] = W[(size_t)kk * Nout + n];
    }
    __syncthreads();
#pragma unroll
    for (int i = 0; i < 32; i += 8) {
        int n = nb + ty + i, kk = kb + tx;
        if (n < Nout && kk < K) Wt[(size_t)n * K + kk] = tile[tx][ty + i];
    }
}

// ======================= tf32 mma.sync GEMM, cp.async double-buffered =======================
// C(fp16)[M,Nout] = A[M,K] @ Wt[Nout,K]^T.  BM=128, BN template (128/64), BK=32.
template <int BN>
__global__ __launch_bounds__(256) void k_gemm_mma(
    const float* __restrict__ A, const float* __restrict__ Bt,
    __half* __restrict__ C, int M, int K, int Nout) {
    constexpr int NT = BN / 16;  // n8-tiles per warp
    __shared__ float sA[2][128][36];
    __shared__ float sB[2][BN][36];

    int t = threadIdx.x;
    int wid = t >> 5, lane = t & 31;
    int grp = lane >> 2, tig = lane & 3;
    int warp_m = wid & 3, warp_n = wid >> 2;
    int m0 = blockIdx.y * 128, n0 = blockIdx.x * BN;

    uint32_t aA = smem_u32(sA);
    uint32_t aB = smem_u32(sB);

    float acc[2][NT][4];
#pragma unroll
    for (int mt = 0; mt < 2; mt++)
#pragma unroll
        for (int nt = 0; nt < NT; nt++)
#pragma unroll
            for (int i = 0; i < 4; i++) acc[mt][nt][i] = 0.0f;

    int nk = K >> 5;

    auto load_tiles = [&](int buf, int k0) {
        // A tile: 128x32 floats = 1024 float4, 4 per thread
#pragma unroll
        for (int i = 0; i < 4; i++) {
            int v = t + i * 256;
            int row = v >> 3, c4 = (v & 7) * 4;
            int grow = m0 + row;
            const float* src = &A[(size_t)((grow < M) ? grow : 0) * K + k0 + c4];
            int sz = (grow < M) ? 16 : 0;
            cp_async16(aA + (uint32_t)(((buf * 128 + row) * 36 + c4) * 4), src, sz);
        }
        // B tile: BNx32 floats = BN/32 * 256 float4
#pragma unroll
        for (int i = 0; i < BN / 32; i++) {
            int v = t + i * 256;
            int row = v >> 3, c4 = (v & 7) * 4;
            const float* src = &Bt[(size_t)(n0 + row) * K + k0 + c4];
            cp_async16(aB + (uint32_t)(((buf * BN + row) * 36 + c4) * 4), src, 16);
        }
    };

    load_tiles(0, 0);
    CP_COMMIT();

    for (int kt = 0; kt < nk; kt++) {
        int buf = kt & 1;
        if (kt + 1 < nk) load_tiles(buf ^ 1, (kt + 1) << 5);
        CP_COMMIT();
        CP_WAIT1();
        __syncthreads();

#pragma unroll
        for (int ks = 0; ks < 4; ks++) {
            int kk = ks * 8;
            uint32_t af[2][4];
#pragma unroll
            for (int mt = 0; mt < 2; mt++) {
                int r = warp_m * 32 + mt * 16;
                af[mt][0] = __float_as_uint(sA[buf][r + grp][kk + tig]);
                af[mt][1] = __float_as_uint(sA[buf][r + grp + 8][kk + tig]);
                af[mt][2] = __float_as_uint(sA[buf][r + grp][kk + tig + 4]);
                af[mt][3] = __float_as_uint(sA[buf][r + grp + 8][kk + tig + 4]);
            }
#pragma unroll
            for (int nt = 0; nt < NT; nt++) {
                int c = warp_n * (NT * 8) + nt * 8;
                uint32_t bf[2];
                bf[0] = __float_as_uint(sB[buf][c + grp][kk + tig]);
                bf[1] = __float_as_uint(sB[buf][c + grp][kk + tig + 4]);
                mma_tf32(acc[0][nt], af[0], bf);
                mma_tf32(acc[1][nt], af[1], bf);
            }
        }
        __syncthreads();
    }

    // epilogue: fp32 acc -> fp16 store
#pragma unroll
    for (int mt = 0; mt < 2; mt++) {
        int r0 = m0 + warp_m * 32 + mt * 16 + grp;
#pragma unroll
        for (int nt = 0; nt < NT; nt++) {
            int col = n0 + warp_n * (NT * 8) + nt * 8 + tig * 2;
            if (r0 < M) {
                __half2 v = __floats2half2_rn(acc[mt][nt][0], acc[mt][nt][1]);
                *(__half2*)&C[(size_t)r0 * Nout + col] = v;
            }
            if (r0 + 8 < M) {
                __half2 v = __floats2half2_rn(acc[mt][nt][2], acc[mt][nt][3]);
                *(__half2*)&C[(size_t)(r0 + 8) * Nout + col] = v;
            }
        }
    }
}

// ======================= CSR gather + bias + relu (fp16 source) =======================
// one block per node, Dout/4 threads, each handles 4 features (uint2 = 4 halves)
__global__ void k_gather(const __half* __restrict__ h, const float* __restrict__ bias,
                         float* __restrict__ out, int Dout) {
    int d = blockIdx.x;
    int f4 = threadIdx.x;

    float wd = g_dis[d];
    float selfw = wd * wd;

    auto load4 = [&](int node) -> float4 {
        uint2 u = ((const uint2*)(h + (size_t)node * Dout))[f4];
        float2 p0 = __half22float2(*(__half2*)&u.x);
        float2 p1 = __half22float2(*(__half2*)&u.y);
        return make_float4(p0.x, p0.y, p1.x, p1.y);
    };

    float4 hv = load4(d);
    float4 acc = make_float4(hv.x * selfw, hv.y * selfw, hv.z * selfw, hv.w * selfw);

    int j = g_off[d];
    int jend = g_off[d + 1];
    for (; j + 1 < jend; j += 2) {
        int sa = g_csrc[j], sb = g_csrc[j + 1];
        float wa = g_cw[j], wb = g_cw[j + 1];
        float4 ha = load4(sa);
        float4 hb = load4(sb);
        acc.x += ha.x * wa + hb.x * wb;
        acc.y += ha.y * wa + hb.y * wb;
        acc.z += ha.z * wa + hb.z * wb;
        acc.w += ha.w * wa + hb.w * wb;
    }
    if (j < jend) {
        int sa = g_csrc[j];
        float wa = g_cw[j];
        float4 ha = load4(sa);
        acc.x += ha.x * wa;
        acc.y += ha.y * wa;
        acc.z += ha.z * wa;
        acc.w += ha.w * wa;
    }

    float4 bv = ((const float4*)bias)[f4];
    acc.x = fmaxf(acc.x + bv.x, 0.0f);
    acc.y = fmaxf(acc.y + bv.y, 0.0f);
    acc.z = fmaxf(acc.z + bv.z, 0.0f);
    acc.w = fmaxf(acc.w + bv.w, 0.0f);
    ((float4*)(out + (size_t)d * Dout))[f4] = acc;
}

// ======================= pool + head =======================
__global__ __launch_bounds__(320) void k_pool(const float* __restrict__ act) {
    int g = blockIdx.x;
    int f = threadIdx.x;
    int n0 = g_goff[g], n1 = g_goff[g + 1];
    float acc = 0.0f;
    for (int n = n0; n < n1; n++) acc += act[(size_t)n * 320 + f];
    float c = (float)(n1 - n0);
    g_pool[g * 320 + f] = acc / fmaxf(c, 1.0f);
}

__global__ __launch_bounds__(256) void k_dense(
    const float* __restrict__ A, const float* __restrict__ W,
    const float* __restrict__ b, float* __restrict__ C,
    int K, int Nout, int relu) {
    __shared__ float row[1024];
    int g = blockIdx.x;
    for (int k = threadIdx.x; k < K; k += blockDim.x) row[k] = A[g * K + k];
    __syncthreads();
    for (int n = threadIdx.x; n < Nout; n += blockDim.x) {
        float s = b[n];
        for (int k = 0; k < K; k++) s += row[k] * W[(size_t)k * Nout + n];
        if (relu) s = fmaxf(s, 0.0f);
        C[g * Nout + n] = s;
    }
}

__global__ void k_concat(const float* __restrict__ fp) {
    int idx = blockIdx.x * blockDim.x + threadIdx.x;
    if (idx < GG * 193) {
        int g = idx / 193;
        int f = idx - g * 193;
        g_cat[idx] = (f < FPD) ? fp[g * FPD + f] : g_t2[g * 128 + (f - FPD)];
    }
}

// ======================= host driver =======================
static void run_layer(const float* X, const float* W, const float* bias,
                      int K, int Dout, __half* hbuf, float* actbuf, float* wtp) {
    dim3 tgrid(Dout / 32, K / 32);
    k_transpose<<<tgrid, 256>>>(W, wtp, K, Dout);
    if (Dout % 128 == 0) {
        dim3 grid(Dout / 128, (NN + 127) / 128);
        k_gemm_mma<128><<<grid, 256>>>(X, wtp, hbuf, NN, K, Dout);
    } else {
        dim3 grid(Dout / 64, (NN + 127) / 128);
        k_gemm_mma<64><<<grid, 256>>>(X, wtp, hbuf, NN, K, Dout);
    }
    k_gather<<<NN, Dout / 4>>>(hbuf, bias, actbuf, Dout);
}

extern "C" void kernel_launch(void* const* d_in, const int* in_sizes, int n_in,
                              void* d_out, int out_size) {
    const float* x     = (const float*)d_in[0];
    const int*   ei    = (const int*)d_in[1];
    const int*   batch = (const int*)d_in[2];
    const float* fp    = (const float*)d_in[3];
    const float* W1 = (const float*)d_in[4];
    const float* b1 = (const float*)d_in[5];
    const float* W2 = (const float*)d_in[6];
    const float* b2 = (const float*)d_in[7];
    const float* W3 = (const float*)d_in[8];
    const float* b3 = (const float*)d_in[9];
    const float* Wg1 = (const float*)d_in[10];
    const float* bg1 = (const float*)d_in[11];
    const float* Wg2 = (const float*)d_in[12];
    const float* bg2 = (const float*)d_in[13];
    const float* Wf1 = (const float*)d_in[14];
    const float* bf1 = (const float*)d_in[15];
    const float* Wf2 = (const float*)d_in[16];
    const float* bf2 = (const float*)d_in[17];
    const float* Wo  = (const float*)d_in[18];
    const float* bo  = (const float*)d_in[19];
    float* out = (float*)d_out;

    const int* src = ei;
    const int* dst = ei + EE;

    float *actbuf, *wtp, *poolp, *t1p, *t2p, *catp, *t3p;
    __half* hbuf;
    int *ecntp, *offp, *curp, *gcntp;
    cudaGetSymbolAddress((void**)&hbuf, g_h);
    cudaGetSymbolAddress((void**)&actbuf, g_act);
    cudaGetSymbolAddress((void**)&wtp, g_wt);
    cudaGetSymbolAddress((void**)&poolp, g_pool);
    cudaGetSymbolAddress((void**)&t1p, g_t1);
    cudaGetSymbolAddress((void**)&t2p, g_t2);
    cudaGetSymbolAddress((void**)&catp, g_cat);
    cudaGetSymbolAddress((void**)&t3p, g_t3);
    cudaGetSymbolAddress((void**)&ecntp, g_ecnt);
    cudaGetSymbolAddress((void**)&offp, g_off);
    cudaGetSymbolAddress((void**)&curp, g_cur);
    cudaGetSymbolAddress((void**)&gcntp, g_gcnt);

    // ---- CSR + norm build ----
    cudaMemsetAsync(ecntp, 0, NN * sizeof(int), 0);
    cudaMemsetAsync(gcntp, 0, GG * sizeof(int), 0);
    k_count<<<(EE + 255) / 256, 256>>>(dst);
    k_dis<<<(NN + 255) / 256, 256>>>();
    k_scan<<<1, 1024>>>();
    cudaMemcpyAsync(curp, offp, NN * sizeof(int), cudaMemcpyDeviceToDevice, 0);
    k_bucket<<<(EE + 255) / 256, 256>>>(src, dst);
    k_gcnt<<<(NN + 255) / 256, 256>>>(batch);
    k_gscan<<<1, 32>>>();

    // ---- three GCN layers ----
    run_layer(x,      W1, b1, DD,  DD,  hbuf, actbuf, wtp);
    run_layer(actbuf, W2, b2, DD,  640, hbuf, actbuf, wtp);
    run_layer(actbuf, W3, b3, 640, 320, hbuf, actbuf, wtp);

    // ---- global mean pool ----
    k_pool<<<GG, 320>>>(actbuf);

    // ---- MLP head ----
    k_dense<<<GG, 256>>>(poolp, Wg1, bg1, t1p, 320, 1024, 1);
    k_dense<<<GG, 256>>>(t1p, Wg2, bg2, t2p, 1024, 128, 0);
    k_concat<<<(GG * 193 + 255) / 256, 256>>>(fp);
    k_dense<<<GG, 256>>>(catp, Wf1, bf1, t1p, 193, 1024, 1);
    k_dense<<<GG, 256>>>(t1p, Wf2, bf2, t3p, 1024, 512, 1);
    k_dense<<<GG, 256>>>(t3p, Wo, bo, out, 512, 1, 0);

    (void)in_sizes; (void)n_in; (void)out_size;
}